// round 16
// baseline (speedup 1.0000x reference)
#include <cuda_runtime.h>

#define N_NODES 100000
#define N_EDGES 3200000
#define NFEAT 128
#define HID 16
#define NC 10
#define NCP2 16   // h2 rows padded to 16 floats (64B, 4x float4)
#define NG 64
#define SCAN_BLK 1024
#define N_SCAN_BLOCKS ((N_NODES + SCAN_BLK - 1) / SCAN_BLK)   // 98
#define GEMM1_BLOCKS ((N_NODES + 63) / 64)                    // 1563

// ---------------- device scratch --------------------------------------------------
__device__ int   g_cnt_i   [N_NODES];      // in-degree (self-cleaned in gather2)
__device__ int   g_rowstart[N_NODES];      // block-local excl scan; used as fill cursor
__device__ int   g_bsum    [N_SCAN_BLOCKS];
__device__ int2  g_csr     [N_EDGES];      // {src, __float_as_int(dinv[src])}
__device__ float g_dinv    [N_NODES];
__device__ float g_h1      [N_NODES * HID];    // x @ W1
__device__ float g_h2      [N_NODES * NCP2];   // relu(conv1) @ W2, padded
__device__ float g_pool    [NG * NC];          // self-cleaned in softmax
__device__ float g_gcnt    [NG];               // self-cleaned in softmax

// redundant per-block exclusive scan of the 98 block sums into smem (cheap: ~100 cyc)
__device__ __forceinline__ void scan_boff(int* sboff /*[128]*/) {
    int t = threadIdx.x;
    int v = 0;
    if (t < 128) {
        v = (t < N_SCAN_BLOCKS) ? g_bsum[t] : 0;
        sboff[t] = v;
    }
    __syncthreads();
#pragma unroll
    for (int off = 1; off < 128; off <<= 1) {
        int add = (t < 128 && t >= off) ? sboff[t - off] : 0;
        __syncthreads();
        if (t < 128) sboff[t] += add;
        __syncthreads();
    }
    if (t < 128) sboff[t] -= v;              // inclusive -> exclusive
    __syncthreads();
}

// ---------------- histogram over dst (standalone; fire-and-forget REDG) --------------
__global__ __launch_bounds__(256) void k_hist(const int* __restrict__ ei) {
    const int4* dst4 = reinterpret_cast<const int4*>(ei + N_EDGES);
    int n4 = N_EDGES / 4;
    int i = blockIdx.x * blockDim.x + threadIdx.x;
    int stride = gridDim.x * blockDim.x;
    for (; i < n4; i += stride) {
        int4 d = dst4[i];
        atomicAdd(&g_cnt_i[d.x], 1);
        atomicAdd(&g_cnt_i[d.y], 1);
        atomicAdd(&g_cnt_i[d.z], 1);
        atomicAdd(&g_cnt_i[d.w], 1);
    }
}

// ---------------- GEMM1 (standalone; runs on side stream, overlapped) ----------------
__global__ __launch_bounds__(256) void k_gemm1(const float* __restrict__ x,
                                               const float* __restrict__ W1) {
    __shared__ float sx[64 * 129];
    __shared__ float sW[NFEAT * HID];

    int tid = threadIdx.x;
    int node0 = blockIdx.x * 64;

    for (int j = tid; j < NFEAT * HID; j += 256) sW[j] = W1[j];

    int nvalid = N_NODES - node0; if (nvalid > 64) nvalid = 64;
    for (int j = tid; j < 64 * NFEAT; j += 256) {
        int r = j / NFEAT, c = j % NFEAT;
        sx[r * 129 + c] = (r < nvalid) ? x[(long long)(node0 + r) * NFEAT + c] : 0.f;
    }
    __syncthreads();

    int n  = tid & 63;
    int og = tid >> 6;
    if (n >= nvalid) return;

    float4 acc0 = make_float4(0.f, 0.f, 0.f, 0.f);
    float4 acc1 = make_float4(0.f, 0.f, 0.f, 0.f);
    const float4* sW4 = reinterpret_cast<const float4*>(sW);
    const float*  xr  = sx + n * 129;
#pragma unroll 8
    for (int k = 0; k < NFEAT; k += 2) {
        float xv0 = xr[k], xv1 = xr[k + 1];
        float4 w0 = sW4[k * 4 + og];
        float4 w1 = sW4[(k + 1) * 4 + og];
        acc0.x += xv0 * w0.x; acc0.y += xv0 * w0.y;
        acc0.z += xv0 * w0.z; acc0.w += xv0 * w0.w;
        acc1.x += xv1 * w1.x; acc1.y += xv1 * w1.y;
        acc1.z += xv1 * w1.z; acc1.w += xv1 * w1.w;
    }
    float4 acc = make_float4(acc0.x + acc1.x, acc0.y + acc1.y,
                             acc0.z + acc1.z, acc0.w + acc1.w);
    reinterpret_cast<float4*>(g_h1 + (node0 + n) * HID)[og] = acc;
}

// ---------------- scan phase 1 (+ dinv) ----------------------------------------------
__global__ __launch_bounds__(SCAN_BLK) void k_scan_block() {
    __shared__ int sh[SCAN_BLK];
    int t = threadIdx.x;
    int i = blockIdx.x * SCAN_BLK + t;
    int v = (i < N_NODES) ? g_cnt_i[i] : 0;
    if (i < N_NODES) g_dinv[i] = rsqrtf((float)v + 1.0f);
    sh[t] = v;
    __syncthreads();
#pragma unroll
    for (int off = 1; off < SCAN_BLK; off <<= 1) {
        int add = (t >= off) ? sh[t - off] : 0;
        __syncthreads();
        sh[t] += add;
        __syncthreads();
    }
    if (i < N_NODES) g_rowstart[i] = sh[t] - v;          // block-local exclusive
    if (t == SCAN_BLK - 1) g_bsum[blockIdx.x] = sh[t];
}

// ---------------- CSR fill: rowstart doubles as cursor (single atomic per edge) --------
__global__ __launch_bounds__(256) void k_fill(const int* __restrict__ ei) {
    __shared__ int sboff[128];
    scan_boff(sboff);

    const int4* s4p = reinterpret_cast<const int4*>(ei);
    const int4* d4p = reinterpret_cast<const int4*>(ei + N_EDGES);
    int i = blockIdx.x * blockDim.x + threadIdx.x;
    int n4 = N_EDGES / 4;
    if (i >= n4) return;
    int4 s = s4p[i];
    int4 d = d4p[i];
    float a0 = g_dinv[s.x], a1 = g_dinv[s.y], a2 = g_dinv[s.z], a3 = g_dinv[s.w];
    int p0 = atomicAdd(&g_rowstart[d.x], 1) + sboff[d.x >> 10];
    int p1 = atomicAdd(&g_rowstart[d.y], 1) + sboff[d.y >> 10];
    int p2 = atomicAdd(&g_rowstart[d.z], 1) + sboff[d.z >> 10];
    int p3 = atomicAdd(&g_rowstart[d.w], 1) + sboff[d.w >> 10];
    g_csr[p0] = make_int2(s.x, __float_as_int(a0));
    g_csr[p1] = make_int2(s.y, __float_as_int(a1));
    g_csr[p2] = make_int2(s.z, __float_as_int(a2));
    g_csr[p3] = make_int2(s.w, __float_as_int(a3));
}

// ---------------- gather1 + combine1 + relu + GEMM2 (4 threads / node, 8-deep) ---------
__global__ __launch_bounds__(256) void k_gather1(const float* __restrict__ b1,
                                                 const float* __restrict__ W2) {
    __shared__ float sW2[HID * NC];
    __shared__ int sboff[128];
    int tid = threadIdx.x;
    if (tid < HID * NC) sW2[tid] = W2[tid];
    scan_boff(sboff);                        // includes __syncthreads barriers

    int gt = blockIdx.x * blockDim.x + tid;
    int node = gt >> 2;
    bool valid = node < N_NODES;
    if (!valid) node = N_NODES - 1;          // clamp; keep lanes alive for shfl
    int part = tid & 3;

    int deg = g_cnt_i[node];
    // post-fill, g_rowstart[node] = block-local exclusive + deg (cursor ran to end)
    int rs  = g_rowstart[node] + sboff[node >> 10] - deg;
    float din = g_dinv[node];

    const int2* sp = g_csr + rs;
    float4 acc = make_float4(0.f, 0.f, 0.f, 0.f);

    int j = 0;
    // ---- 8-deep main loop: 8 independent row loads in flight per thread ----
    for (; j + 16 <= deg; j += 8) {
        int2 p0 = sp[j + 0], p1 = sp[j + 1], p2 = sp[j + 2], p3 = sp[j + 3];
        int2 p4 = sp[j + 4], p5 = sp[j + 5], p6 = sp[j + 6], p7 = sp[j + 7];
        float4 v0 = *reinterpret_cast<const float4*>(g_h1 + p0.x * HID + part * 4);
        float4 v1 = *reinterpret_cast<const float4*>(g_h1 + p1.x * HID + part * 4);
        float4 v2 = *reinterpret_cast<const float4*>(g_h1 + p2.x * HID + part * 4);
        float4 v3 = *reinterpret_cast<const float4*>(g_h1 + p3.x * HID + part * 4);
        float4 v4 = *reinterpret_cast<const float4*>(g_h1 + p4.x * HID + part * 4);
        float4 v5 = *reinterpret_cast<const float4*>(g_h1 + p5.x * HID + part * 4);
        float4 v6 = *reinterpret_cast<const float4*>(g_h1 + p6.x * HID + part * 4);
        float4 v7 = *reinterpret_cast<const float4*>(g_h1 + p7.x * HID + part * 4);
        float c0 = din * __int_as_float(p0.y);
        float c1 = din * __int_as_float(p1.y);
        float c2 = din * __int_as_float(p2.y);
        float c3 = din * __int_as_float(p3.y);
        float c4 = din * __int_as_float(p4.y);
        float c5 = din * __int_as_float(p5.y);
        float c6 = din * __int_as_float(p6.y);
        float c7 = din * __int_as_float(p7.y);
        acc.x += v0.x * c0; acc.y += v0.y * c0; acc.z += v0.z * c0; acc.w += v0.w * c0;
        acc.x += v1.x * c1; acc.y += v1.y * c1; acc.z += v1.z * c1; acc.w += v1.w * c1;
        acc.x += v2.x * c2; acc.y += v2.y * c2; acc.z += v2.z * c2; acc.w += v2.w * c2;
        acc.x += v3.x * c3; acc.y += v3.y * c3; acc.z += v3.z * c3; acc.w += v3.w * c3;
        acc.x += v4.x * c4; acc.y += v4.y * c4; acc.z += v4.z * c4; acc.w += v4.w * c4;
        acc.x += v5.x * c5; acc.y += v5.y * c5; acc.z += v5.z * c5; acc.w += v5.w * c5;
        acc.x += v6.x * c6; acc.y += v6.y * c6; acc.z += v6.z * c6; acc.w += v6.w * c6;
        acc.x += v7.x * c7; acc.y += v7.y * c7; acc.z += v7.z * c7; acc.w += v7.w * c7;
    }
    for (; j + 4 <= deg; j += 4) {
        int2 p0 = sp[j + 0], p1 = sp[j + 1], p2 = sp[j + 2], p3 = sp[j + 3];
        float4 v0 = *reinterpret_cast<const float4*>(g_h1 + p0.x * HID + part * 4);
        float4 v1 = *reinterpret_cast<const float4*>(g_h1 + p1.x * HID + part * 4);
        float4 v2 = *reinterpret_cast<const float4*>(g_h1 + p2.x * HID + part * 4);
        float4 v3 = *reinterpret_cast<const float4*>(g_h1 + p3.x * HID + part * 4);
        float c0 = din * __int_as_float(p0.y);
        float c1 = din * __int_as_float(p1.y);
        float c2 = din * __int_as_float(p2.y);
        float c3 = din * __int_as_float(p3.y);
        acc.x += v0.x * c0; acc.y += v0.y * c0; acc.z += v0.z * c0; acc.w += v0.w * c0;
        acc.x += v1.x * c1; acc.y += v1.y * c1; acc.z += v1.z * c1; acc.w += v1.w * c1;
        acc.x += v2.x * c2; acc.y += v2.y * c2; acc.z += v2.z * c2; acc.w += v2.w * c2;
        acc.x += v3.x * c3; acc.y += v3.y * c3; acc.z += v3.z * c3; acc.w += v3.w * c3;
    }
    for (; j < deg; j++) {
        int2 p = sp[j];
        float c = din * __int_as_float(p.y);
        float4 v = *reinterpret_cast<const float4*>(g_h1 + p.x * HID + part * 4);
        acc.x += v.x * c; acc.y += v.y * c; acc.z += v.z * c; acc.w += v.w * c;
    }

    // combine + relu -> this thread's 4-wide slice of hr
    float sl = din * din;
    float4 h = *reinterpret_cast<const float4*>(g_h1 + node * HID + part * 4);
    float4 b = reinterpret_cast<const float4*>(b1)[part];
    float4 a;
    a.x = fmaxf(acc.x + h.x * sl + b.x, 0.f);
    a.y = fmaxf(acc.y + h.y * sl + b.y, 0.f);
    a.z = fmaxf(acc.z + h.z * sl + b.z, 0.f);
    a.w = fmaxf(acc.w + h.w * sl + b.w, 0.f);

    // exchange the 16-wide hr row among the 4 lanes of this node
    float hr[HID];
    unsigned lanebase = (unsigned)(tid & 31) & ~3u;
#pragma unroll
    for (int q = 0; q < 4; q++) {
        hr[q * 4 + 0] = __shfl_sync(0xffffffffu, a.x, lanebase + q);
        hr[q * 4 + 1] = __shfl_sync(0xffffffffu, a.y, lanebase + q);
        hr[q * 4 + 2] = __shfl_sync(0xffffffffu, a.z, lanebase + q);
        hr[q * 4 + 3] = __shfl_sync(0xffffffffu, a.w, lanebase + q);
    }

    // gemm2: this thread computes output cols [part*4, part*4+4)
    float4 o = make_float4(0.f, 0.f, 0.f, 0.f);
    float* op = &o.x;
#pragma unroll
    for (int c = 0; c < 4; c++) {
        int col = part * 4 + c;
        if (col < NC) {
            float s = 0.f;
#pragma unroll
            for (int k = 0; k < HID; k++) s += hr[k] * sW2[k * NC + col];
            op[c] = s;
        }
    }
    if (valid)
        *reinterpret_cast<float4*>(g_h2 + node * NCP2 + part * 4) = o;
}

// ---------------- gather2 + combine2 + mean-pool (4 threads / node, 8-deep) ------------
__global__ __launch_bounds__(256) void k_gather2(const float* __restrict__ b2,
                                                 const int* __restrict__ batch) {
    __shared__ int sboff[128];
    scan_boff(sboff);                        // all threads run prologue before any return

    int gt = blockIdx.x * blockDim.x + threadIdx.x;
    int node = gt >> 2;
    if (node >= N_NODES) return;
    int part = gt & 3;

    int deg = g_cnt_i[node];
    int rs  = g_rowstart[node] + sboff[node >> 10] - deg;
    float din = g_dinv[node];
    int g = batch[node];

    const int2* sp = g_csr + rs;
    float4 acc = make_float4(0.f, 0.f, 0.f, 0.f);

    int j = 0;
    for (; j + 16 <= deg; j += 8) {
        int2 p0 = sp[j + 0], p1 = sp[j + 1], p2 = sp[j + 2], p3 = sp[j + 3];
        int2 p4 = sp[j + 4], p5 = sp[j + 5], p6 = sp[j + 6], p7 = sp[j + 7];
        float4 v0 = *reinterpret_cast<const float4*>(g_h2 + p0.x * NCP2 + part * 4);
        float4 v1 = *reinterpret_cast<const float4*>(g_h2 + p1.x * NCP2 + part * 4);
        float4 v2 = *reinterpret_cast<const float4*>(g_h2 + p2.x * NCP2 + part * 4);
        float4 v3 = *reinterpret_cast<const float4*>(g_h2 + p3.x * NCP2 + part * 4);
        float4 v4 = *reinterpret_cast<const float4*>(g_h2 + p4.x * NCP2 + part * 4);
        float4 v5 = *reinterpret_cast<const float4*>(g_h2 + p5.x * NCP2 + part * 4);
        float4 v6 = *reinterpret_cast<const float4*>(g_h2 + p6.x * NCP2 + part * 4);
        float4 v7 = *reinterpret_cast<const float4*>(g_h2 + p7.x * NCP2 + part * 4);
        float c0 = din * __int_as_float(p0.y);
        float c1 = din * __int_as_float(p1.y);
        float c2 = din * __int_as_float(p2.y);
        float c3 = din * __int_as_float(p3.y);
        float c4 = din * __int_as_float(p4.y);
        float c5 = din * __int_as_float(p5.y);
        float c6 = din * __int_as_float(p6.y);
        float c7 = din * __int_as_float(p7.y);
        acc.x += v0.x * c0; acc.y += v0.y * c0; acc.z += v0.z * c0; acc.w += v0.w * c0;
        acc.x += v1.x * c1; acc.y += v1.y * c1; acc.z += v1.z * c1; acc.w += v1.w * c1;
        acc.x += v2.x * c2; acc.y += v2.y * c2; acc.z += v2.z * c2; acc.w += v2.w * c2;
        acc.x += v3.x * c3; acc.y += v3.y * c3; acc.z += v3.z * c3; acc.w += v3.w * c3;
        acc.x += v4.x * c4; acc.y += v4.y * c4; acc.z += v4.z * c4; acc.w += v4.w * c4;
        acc.x += v5.x * c5; acc.y += v5.y * c5; acc.z += v5.z * c5; acc.w += v5.w * c5;
        acc.x += v6.x * c6; acc.y += v6.y * c6; acc.z += v6.z * c6; acc.w += v6.w * c6;
        acc.x += v7.x * c7; acc.y += v7.y * c7; acc.z += v7.z * c7; acc.w += v7.w * c7;
    }
    for (; j + 4 <= deg; j += 4) {
        int2 p0 = sp[j + 0], p1 = sp[j + 1], p2 = sp[j + 2], p3 = sp[j + 3];
        float4 v0 = *reinterpret_cast<const float4*>(g_h2 + p0.x * NCP2 + part * 4);
        float4 v1 = *reinterpret_cast<const float4*>(g_h2 + p1.x * NCP2 + part * 4);
        float4 v2 = *reinterpret_cast<const float4*>(g_h2 + p2.x * NCP2 + part * 4);
        float4 v3 = *reinterpret_cast<const float4*>(g_h2 + p3.x * NCP2 + part * 4);
        float c0 = din * __int_as_float(p0.y);
        float c1 = din * __int_as_float(p1.y);
        float c2 = din * __int_as_float(p2.y);
        float c3 = din * __int_as_float(p3.y);
        acc.x += v0.x * c0; acc.y += v0.y * c0; acc.z += v0.z * c0; acc.w += v0.w * c0;
        acc.x += v1.x * c1; acc.y += v1.y * c1; acc.z += v1.z * c1; acc.w += v1.w * c1;
        acc.x += v2.x * c2; acc.y += v2.y * c2; acc.z += v2.z * c2; acc.w += v2.w * c2;
        acc.x += v3.x * c3; acc.y += v3.y * c3; acc.z += v3.z * c3; acc.w += v3.w * c3;
    }
    for (; j < deg; j++) {
        int2 p = sp[j];
        float c = din * __int_as_float(p.y);
        float4 v = *reinterpret_cast<const float4*>(g_h2 + p.x * NCP2 + part * 4);
        acc.x += v.x * c; acc.y += v.y * c; acc.z += v.z * c; acc.w += v.w * c;
    }

    float sl = din * din;
    float4 h = *reinterpret_cast<const float4*>(g_h2 + node * NCP2 + part * 4);
    float* pool = g_pool + g * NC;

    float res[4] = { acc.x + h.x * sl, acc.y + h.y * sl,
                     acc.z + h.z * sl, acc.w + h.w * sl };
#pragma unroll
    for (int c = 0; c < 4; c++) {
        int col = part * 4 + c;
        if (col < NC) atomicAdd(pool + col, res[c] + b2[col]);
    }
    if (part == 0) {
        atomicAdd(&g_gcnt[g], 1.0f);
        g_cnt_i[node] = 0;                    // self-clean for next call
    }
}

// ---------------- finalize: mean + log_softmax (+ self-clean pool) ----------------------
__global__ void k_softmax(float* __restrict__ out) {
    int g = threadIdx.x;
    if (g >= NG) return;
    float cnt = fmaxf(g_gcnt[g], 1.0f);
    float p[NC];
    float m = -1e30f;
#pragma unroll
    for (int o = 0; o < NC; o++) { p[o] = g_pool[g * NC + o] / cnt; m = fmaxf(m, p[o]); }
    float s = 0.f;
#pragma unroll
    for (int o = 0; o < NC; o++) s += __expf(p[o] - m);
    float l = logf(s);
#pragma unroll
    for (int o = 0; o < NC; o++) {
        out[g * NC + o] = p[o] - m - l;
        g_pool[g * NC + o] = 0.f;             // self-clean for next call
    }
    g_gcnt[g] = 0.f;
}

// ---------------- side-stream infrastructure (created once, pre-main; no device mem) ----
struct SideStream {
    cudaStream_t s = nullptr;
    cudaEvent_t  fork = nullptr, join = nullptr;
    bool ok = false;
    SideStream() {
        ok = (cudaStreamCreateWithFlags(&s, cudaStreamNonBlocking) == cudaSuccess) &&
             (cudaEventCreateWithFlags(&fork, cudaEventDisableTiming) == cudaSuccess) &&
             (cudaEventCreateWithFlags(&join, cudaEventDisableTiming) == cudaSuccess);
    }
};
static SideStream g_ss;

// ---------------- launcher ----------------------------------------------------------------
extern "C" void kernel_launch(void* const* d_in, const int* in_sizes, int n_in,
                              void* d_out, int out_size) {
    const float* x     = (const float*)d_in[0];
    const int*   ei    = (const int*)d_in[1];    // int32 (jax default int)
    const int*   batch = (const int*)d_in[2];
    const float* W1    = (const float*)d_in[3];
    const float* b1    = (const float*)d_in[4];
    const float* W2    = (const float*)d_in[5];
    const float* b2    = (const float*)d_in[6];
    float* out = (float*)d_out;

    const int TB = 256;
    const int node4Blocks = (4 * N_NODES + TB - 1) / TB;      // 1563
    const int fillBlocks  = (N_EDGES / 4 + TB - 1) / TB;      // 3125

    // Branch A (default stream): hist -> scan -> fill (latency/atomic bound, ~80us)
    // Branch B (side stream):    gemm1 (FMA/smem bound, ~37us) -- fully independent
    k_hist<<<2048, TB>>>(ei);                                         // launch 1

    bool forked = g_ss.ok;
    if (forked) {
        cudaEventRecord(g_ss.fork, 0);
        cudaStreamWaitEvent(g_ss.s, g_ss.fork, 0);
        k_gemm1<<<GEMM1_BLOCKS, TB, 0, g_ss.s>>>(x, W1);              // launch 2 (side)
        cudaEventRecord(g_ss.join, g_ss.s);
    } else {
        k_gemm1<<<GEMM1_BLOCKS, TB>>>(x, W1);                         // sequential fallback
    }

    k_scan_block<<<N_SCAN_BLOCKS, SCAN_BLK>>>();                      // launch 3
    k_fill<<<fillBlocks, TB>>>(ei);                                   // launch 4 <- ncu slot

    if (forked) cudaStreamWaitEvent(0, g_ss.join, 0);                 // join before gather1
    k_gather1<<<node4Blocks, TB>>>(b1, W2);                           // launch 5
    k_gather2<<<node4Blocks, TB>>>(b2, batch);                        // launch 6
    k_softmax<<<1, 64>>>(out);                                        // launch 7
}

// round 17
// speedup vs baseline: 1.0667x; 1.0667x over previous
#include <cuda_runtime.h>

#define N_NODES 100000
#define N_EDGES 3200000
#define NFEAT 128
#define HID 16
#define NC 10
#define NCP2 16   // h2 rows padded to 16 floats (64B, 4x float4)
#define NG 64
#define SCAN_BLK 1024
#define N_SCAN_BLOCKS ((N_NODES + SCAN_BLK - 1) / SCAN_BLK)   // 98

#define GEMM1_BLOCKS ((N_NODES + 63) / 64)          // 1563 = 3 * 521
#define PRE1_QUADS   (GEMM1_BLOCKS / 3)             // 521 (3 gemm + 1 hist per quad)
#define PRE1_BLOCKS  (PRE1_QUADS * 4)               // 2084

// ---------------- device scratch --------------------------------------------------
__device__ int   g_cnt_i   [N_NODES];      // in-degree histogram over dst (self-cleaned)
__device__ int   g_rowstart[N_NODES];      // exclusive prefix sum
__device__ int   g_cur     [N_NODES];      // fill cursors (re-inited each call)
__device__ int   g_bsum    [N_SCAN_BLOCKS];
__device__ int2  g_csr     [N_EDGES];      // {src, __float_as_int(dinv[src])}
__device__ float g_dinv    [N_NODES];
__device__ float g_h1      [N_NODES * HID];    // x @ W1
__device__ float g_h2      [N_NODES * NCP2];   // relu(conv1) @ W2, padded
__device__ float g_pool    [NG * NC];          // self-cleaned in softmax
__device__ float g_gcnt    [NG];               // self-cleaned in softmax

// ---------------- fused: GEMM1 (3/4 of blocks) + dst-histogram (1/4) ---------------
// Known-best structure: hist atomics fire-and-forget (REDG), hidden under gemm1.
__global__ __launch_bounds__(256) void k_pre1(const float* __restrict__ x,
                                              const float* __restrict__ W1,
                                              const int* __restrict__ ei) {
    __shared__ float sx[64 * 129];
    __shared__ float sW[NFEAT * HID];

    int b = blockIdx.x;
    int tid = threadIdx.x;

    if ((b & 3) == 3) {
        // ---- histogram role: grid-stride over dst half as int4 ----
        const int4* dst4 = reinterpret_cast<const int4*>(ei + N_EDGES);
        int n4 = N_EDGES / 4;
        int i = (b >> 2) * 256 + tid;
        int stride = PRE1_QUADS * 256;
        for (; i < n4; i += stride) {
            int4 d = dst4[i];
            atomicAdd(&g_cnt_i[d.x], 1);
            atomicAdd(&g_cnt_i[d.y], 1);
            atomicAdd(&g_cnt_i[d.z], 1);
            atomicAdd(&g_cnt_i[d.w], 1);
        }
        return;
    }

    // ---- gemm1 role ----
    int gb = (b >> 2) * 3 + (b & 3);      // 0..GEMM1_BLOCKS-1
    int node0 = gb * 64;

    for (int j = tid; j < NFEAT * HID; j += 256) sW[j] = W1[j];

    int nvalid = N_NODES - node0; if (nvalid > 64) nvalid = 64;
    for (int j = tid; j < 64 * NFEAT; j += 256) {
        int r = j / NFEAT, c = j % NFEAT;
        sx[r * 129 + c] = (r < nvalid) ? x[(long long)(node0 + r) * NFEAT + c] : 0.f;
    }
    __syncthreads();

    int n  = tid & 63;
    int og = tid >> 6;
    if (n >= nvalid) return;

    float4 acc0 = make_float4(0.f, 0.f, 0.f, 0.f);
    float4 acc1 = make_float4(0.f, 0.f, 0.f, 0.f);
    const float4* sW4 = reinterpret_cast<const float4*>(sW);
    const float*  xr  = sx + n * 129;
#pragma unroll 8
    for (int k = 0; k < NFEAT; k += 2) {
        float xv0 = xr[k], xv1 = xr[k + 1];
        float4 w0 = sW4[k * 4 + og];
        float4 w1 = sW4[(k + 1) * 4 + og];
        acc0.x += xv0 * w0.x; acc0.y += xv0 * w0.y;
        acc0.z += xv0 * w0.z; acc0.w += xv0 * w0.w;
        acc1.x += xv1 * w1.x; acc1.y += xv1 * w1.y;
        acc1.z += xv1 * w1.z; acc1.w += xv1 * w1.w;
    }
    float4 acc = make_float4(acc0.x + acc1.x, acc0.y + acc1.y,
                             acc0.z + acc1.z, acc0.w + acc1.w);
    reinterpret_cast<float4*>(g_h1 + (node0 + n) * HID)[og] = acc;
}

// ---------------- scan phase 1 (+ dinv) ----------------------------------------------
__global__ __launch_bounds__(SCAN_BLK) void k_scan_block() {
    __shared__ int sh[SCAN_BLK];
    int t = threadIdx.x;
    int i = blockIdx.x * SCAN_BLK + t;
    int v = (i < N_NODES) ? g_cnt_i[i] : 0;
    if (i < N_NODES) g_dinv[i] = rsqrtf((float)v + 1.0f);
    sh[t] = v;
    __syncthreads();
#pragma unroll
    for (int off = 1; off < SCAN_BLK; off <<= 1) {
        int add = (t >= off) ? sh[t - off] : 0;
        __syncthreads();
        sh[t] += add;
        __syncthreads();
    }
    if (i < N_NODES) g_rowstart[i] = sh[t] - v;          // block-local exclusive
    if (t == SCAN_BLK - 1) g_bsum[blockIdx.x] = sh[t];
}

// ---------------- scan finish: per-block redundant bsum scan + offset + cursor init ---
__global__ __launch_bounds__(256) void k_scan_finish() {
    __shared__ int sb[128];
    int t = threadIdx.x;
    if (t < 128) sb[t] = (t < N_SCAN_BLOCKS) ? g_bsum[t] : 0;
    __syncthreads();
#pragma unroll
    for (int off = 1; off < 128; off <<= 1) {
        int add = (t < 128 && t >= off) ? sb[t - off] : 0;
        __syncthreads();
        if (t < 128) sb[t] += add;
        __syncthreads();
    }
    int i = blockIdx.x * 256 + t;
    if (i < N_NODES) {
        int blk = i >> 10;
        int excl = sb[blk] - g_bsum[blk];       // inclusive -> exclusive
        int rs = g_rowstart[i] + excl;
        g_rowstart[i] = rs;
        g_cur[i] = rs;
    }
}

// ---------------- CSR fill: 8 edges/thread via 2x int4 (MLP=8 on cursor atomics) -------
__global__ __launch_bounds__(256) void k_fill(const int* __restrict__ ei) {
    const int4* s4p = reinterpret_cast<const int4*>(ei);
    const int4* d4p = reinterpret_cast<const int4*>(ei + N_EDGES);
    int i = blockIdx.x * blockDim.x + threadIdx.x;
    int n8 = N_EDGES / 8;
    if (i >= n8) return;
    int4 sa = s4p[2 * i],     da = d4p[2 * i];
    int4 sb = s4p[2 * i + 1], db = d4p[2 * i + 1];
    float a0 = g_dinv[sa.x], a1 = g_dinv[sa.y], a2 = g_dinv[sa.z], a3 = g_dinv[sa.w];
    float a4 = g_dinv[sb.x], a5 = g_dinv[sb.y], a6 = g_dinv[sb.z], a7 = g_dinv[sb.w];
    int p0 = atomicAdd(&g_cur[da.x], 1);
    int p1 = atomicAdd(&g_cur[da.y], 1);
    int p2 = atomicAdd(&g_cur[da.z], 1);
    int p3 = atomicAdd(&g_cur[da.w], 1);
    int p4 = atomicAdd(&g_cur[db.x], 1);
    int p5 = atomicAdd(&g_cur[db.y], 1);
    int p6 = atomicAdd(&g_cur[db.z], 1);
    int p7 = atomicAdd(&g_cur[db.w], 1);
    g_csr[p0] = make_int2(sa.x, __float_as_int(a0));
    g_csr[p1] = make_int2(sa.y, __float_as_int(a1));
    g_csr[p2] = make_int2(sa.z, __float_as_int(a2));
    g_csr[p3] = make_int2(sa.w, __float_as_int(a3));
    g_csr[p4] = make_int2(sb.x, __float_as_int(a4));
    g_csr[p5] = make_int2(sb.y, __float_as_int(a5));
    g_csr[p6] = make_int2(sb.z, __float_as_int(a6));
    g_csr[p7] = make_int2(sb.w, __float_as_int(a7));
}

// ---------------- gather1 + combine1 + relu + GEMM2 (4 threads / node, 8-deep) ---------
__global__ __launch_bounds__(256) void k_gather1(const float* __restrict__ b1,
                                                 const float* __restrict__ W2) {
    __shared__ float sW2[HID * NC];
    int tid = threadIdx.x;
    if (tid < HID * NC) sW2[tid] = W2[tid];
    __syncthreads();

    int gt = blockIdx.x * blockDim.x + tid;
    int node = gt >> 2;
    bool valid = node < N_NODES;
    if (!valid) node = N_NODES - 1;          // clamp; keep lanes alive for shfl
    int part = tid & 3;

    int rs  = g_rowstart[node];
    int deg = g_cnt_i[node];
    float din = g_dinv[node];

    const int2* sp = g_csr + rs;
    float4 acc = make_float4(0.f, 0.f, 0.f, 0.f);

    int j = 0;
    // ---- 8-deep main loop: 8 independent row loads in flight per thread ----
    for (; j + 16 <= deg; j += 8) {
        int2 p0 = sp[j + 0], p1 = sp[j + 1], p2 = sp[j + 2], p3 = sp[j + 3];
        int2 p4 = sp[j + 4], p5 = sp[j + 5], p6 = sp[j + 6], p7 = sp[j + 7];
        float4 v0 = *reinterpret_cast<const float4*>(g_h1 + p0.x * HID + part * 4);
        float4 v1 = *reinterpret_cast<const float4*>(g_h1 + p1.x * HID + part * 4);
        float4 v2 = *reinterpret_cast<const float4*>(g_h1 + p2.x * HID + part * 4);
        float4 v3 = *reinterpret_cast<const float4*>(g_h1 + p3.x * HID + part * 4);
        float4 v4 = *reinterpret_cast<const float4*>(g_h1 + p4.x * HID + part * 4);
        float4 v5 = *reinterpret_cast<const float4*>(g_h1 + p5.x * HID + part * 4);
        float4 v6 = *reinterpret_cast<const float4*>(g_h1 + p6.x * HID + part * 4);
        float4 v7 = *reinterpret_cast<const float4*>(g_h1 + p7.x * HID + part * 4);
        float c0 = din * __int_as_float(p0.y);
        float c1 = din * __int_as_float(p1.y);
        float c2 = din * __int_as_float(p2.y);
        float c3 = din * __int_as_float(p3.y);
        float c4 = din * __int_as_float(p4.y);
        float c5 = din * __int_as_float(p5.y);
        float c6 = din * __int_as_float(p6.y);
        float c7 = din * __int_as_float(p7.y);
        acc.x += v0.x * c0; acc.y += v0.y * c0; acc.z += v0.z * c0; acc.w += v0.w * c0;
        acc.x += v1.x * c1; acc.y += v1.y * c1; acc.z += v1.z * c1; acc.w += v1.w * c1;
        acc.x += v2.x * c2; acc.y += v2.y * c2; acc.z += v2.z * c2; acc.w += v2.w * c2;
        acc.x += v3.x * c3; acc.y += v3.y * c3; acc.z += v3.z * c3; acc.w += v3.w * c3;
        acc.x += v4.x * c4; acc.y += v4.y * c4; acc.z += v4.z * c4; acc.w += v4.w * c4;
        acc.x += v5.x * c5; acc.y += v5.y * c5; acc.z += v5.z * c5; acc.w += v5.w * c5;
        acc.x += v6.x * c6; acc.y += v6.y * c6; acc.z += v6.z * c6; acc.w += v6.w * c6;
        acc.x += v7.x * c7; acc.y += v7.y * c7; acc.z += v7.z * c7; acc.w += v7.w * c7;
    }
    // ---- 4-wide cleanup ----
    for (; j + 4 <= deg; j += 4) {
        int2 p0 = sp[j + 0], p1 = sp[j + 1], p2 = sp[j + 2], p3 = sp[j + 3];
        float4 v0 = *reinterpret_cast<const float4*>(g_h1 + p0.x * HID + part * 4);
        float4 v1 = *reinterpret_cast<const float4*>(g_h1 + p1.x * HID + part * 4);
        float4 v2 = *reinterpret_cast<const float4*>(g_h1 + p2.x * HID + part * 4);
        float4 v3 = *reinterpret_cast<const float4*>(g_h1 + p3.x * HID + part * 4);
        float c0 = din * __int_as_float(p0.y);
        float c1 = din * __int_as_float(p1.y);
        float c2 = din * __int_as_float(p2.y);
        float c3 = din * __int_as_float(p3.y);
        acc.x += v0.x * c0; acc.y += v0.y * c0; acc.z += v0.z * c0; acc.w += v0.w * c0;
        acc.x += v1.x * c1; acc.y += v1.y * c1; acc.z += v1.z * c1; acc.w += v1.w * c1;
        acc.x += v2.x * c2; acc.y += v2.y * c2; acc.z += v2.z * c2; acc.w += v2.w * c2;
        acc.x += v3.x * c3; acc.y += v3.y * c3; acc.z += v3.z * c3; acc.w += v3.w * c3;
    }
    for (; j < deg; j++) {
        int2 p = sp[j];
        float c = din * __int_as_float(p.y);
        float4 v = *reinterpret_cast<const float4*>(g_h1 + p.x * HID + part * 4);
        acc.x += v.x * c; acc.y += v.y * c; acc.z += v.z * c; acc.w += v.w * c;
    }

    // combine + relu -> this thread's 4-wide slice of hr
    float sl = din * din;
    float4 h = *reinterpret_cast<const float4*>(g_h1 + node * HID + part * 4);
    float4 b = reinterpret_cast<const float4*>(b1)[part];
    float4 a;
    a.x = fmaxf(acc.x + h.x * sl + b.x, 0.f);
    a.y = fmaxf(acc.y + h.y * sl + b.y, 0.f);
    a.z = fmaxf(acc.z + h.z * sl + b.z, 0.f);
    a.w = fmaxf(acc.w + h.w * sl + b.w, 0.f);

    // exchange the 16-wide hr row among the 4 lanes of this node
    float hr[HID];
    unsigned lanebase = (unsigned)(tid & 31) & ~3u;
#pragma unroll
    for (int q = 0; q < 4; q++) {
        hr[q * 4 + 0] = __shfl_sync(0xffffffffu, a.x, lanebase + q);
        hr[q * 4 + 1] = __shfl_sync(0xffffffffu, a.y, lanebase + q);
        hr[q * 4 + 2] = __shfl_sync(0xffffffffu, a.z, lanebase + q);
        hr[q * 4 + 3] = __shfl_sync(0xffffffffu, a.w, lanebase + q);
    }

    // gemm2: this thread computes output cols [part*4, part*4+4)
    float4 o = make_float4(0.f, 0.f, 0.f, 0.f);
    float* op = &o.x;
#pragma unroll
    for (int c = 0; c < 4; c++) {
        int col = part * 4 + c;
        if (col < NC) {
            float s = 0.f;
#pragma unroll
            for (int k = 0; k < HID; k++) s += hr[k] * sW2[k * NC + col];
            op[c] = s;
        }
    }
    if (valid)
        *reinterpret_cast<float4*>(g_h2 + node * NCP2 + part * 4) = o;
}

// ---------------- gather2 + combine2 + mean-pool (4 threads / node, 8-deep pipeline) ---
__global__ __launch_bounds__(256) void k_gather2(const float* __restrict__ b2,
                                                 const int* __restrict__ batch) {
    int gt = blockIdx.x * blockDim.x + threadIdx.x;
    int node = gt >> 2;
    if (node >= N_NODES) return;
    int part = gt & 3;

    int rs  = g_rowstart[node];
    int deg = g_cnt_i[node];
    float din = g_dinv[node];
    int g = batch[node];

    const int2* sp = g_csr + rs;
    float4 acc = make_float4(0.f, 0.f, 0.f, 0.f);

    int j = 0;
    // ---- 8-deep main loop: 8 independent row loads in flight per thread ----
    for (; j + 16 <= deg; j += 8) {
        int2 p0 = sp[j + 0], p1 = sp[j + 1], p2 = sp[j + 2], p3 = sp[j + 3];
        int2 p4 = sp[j + 4], p5 = sp[j + 5], p6 = sp[j + 6], p7 = sp[j + 7];
        float4 v0 = *reinterpret_cast<const float4*>(g_h2 + p0.x * NCP2 + part * 4);
        float4 v1 = *reinterpret_cast<const float4*>(g_h2 + p1.x * NCP2 + part * 4);
        float4 v2 = *reinterpret_cast<const float4*>(g_h2 + p2.x * NCP2 + part * 4);
        float4 v3 = *reinterpret_cast<const float4*>(g_h2 + p3.x * NCP2 + part * 4);
        float4 v4 = *reinterpret_cast<const float4*>(g_h2 + p4.x * NCP2 + part * 4);
        float4 v5 = *reinterpret_cast<const float4*>(g_h2 + p5.x * NCP2 + part * 4);
        float4 v6 = *reinterpret_cast<const float4*>(g_h2 + p6.x * NCP2 + part * 4);
        float4 v7 = *reinterpret_cast<const float4*>(g_h2 + p7.x * NCP2 + part * 4);
        float c0 = din * __int_as_float(p0.y);
        float c1 = din * __int_as_float(p1.y);
        float c2 = din * __int_as_float(p2.y);
        float c3 = din * __int_as_float(p3.y);
        float c4 = din * __int_as_float(p4.y);
        float c5 = din * __int_as_float(p5.y);
        float c6 = din * __int_as_float(p6.y);
        float c7 = din * __int_as_float(p7.y);
        acc.x += v0.x * c0; acc.y += v0.y * c0; acc.z += v0.z * c0; acc.w += v0.w * c0;
        acc.x += v1.x * c1; acc.y += v1.y * c1; acc.z += v1.z * c1; acc.w += v1.w * c1;
        acc.x += v2.x * c2; acc.y += v2.y * c2; acc.z += v2.z * c2; acc.w += v2.w * c2;
        acc.x += v3.x * c3; acc.y += v3.y * c3; acc.z += v3.z * c3; acc.w += v3.w * c3;
        acc.x += v4.x * c4; acc.y += v4.y * c4; acc.z += v4.z * c4; acc.w += v4.w * c4;
        acc.x += v5.x * c5; acc.y += v5.y * c5; acc.z += v5.z * c5; acc.w += v5.w * c5;
        acc.x += v6.x * c6; acc.y += v6.y * c6; acc.z += v6.z * c6; acc.w += v6.w * c6;
        acc.x += v7.x * c7; acc.y += v7.y * c7; acc.z += v7.z * c7; acc.w += v7.w * c7;
    }
    // ---- 4-wide cleanup ----
    for (; j + 4 <= deg; j += 4) {
        int2 p0 = sp[j + 0], p1 = sp[j + 1], p2 = sp[j + 2], p3 = sp[j + 3];
        float4 v0 = *reinterpret_cast<const float4*>(g_h2 + p0.x * NCP2 + part * 4);
        float4 v1 = *reinterpret_cast<const float4*>(g_h2 + p1.x * NCP2 + part * 4);
        float4 v2 = *reinterpret_cast<const float4*>(g_h2 + p2.x * NCP2 + part * 4);
        float4 v3 = *reinterpret_cast<const float4*>(g_h2 + p3.x * NCP2 + part * 4);
        float c0 = din * __int_as_float(p0.y);
        float c1 = din * __int_as_float(p1.y);
        float c2 = din * __int_as_float(p2.y);
        float c3 = din * __int_as_float(p3.y);
        acc.x += v0.x * c0; acc.y += v0.y * c0; acc.z += v0.z * c0; acc.w += v0.w * c0;
        acc.x += v1.x * c1; acc.y += v1.y * c1; acc.z += v1.z * c1; acc.w += v1.w * c1;
        acc.x += v2.x * c2; acc.y += v2.y * c2; acc.z += v2.z * c2; acc.w += v2.w * c2;
        acc.x += v3.x * c3; acc.y += v3.y * c3; acc.z += v3.z * c3; acc.w += v3.w * c3;
    }
    for (; j < deg; j++) {
        int2 p = sp[j];
        float c = din * __int_as_float(p.y);
        float4 v = *reinterpret_cast<const float4*>(g_h2 + p.x * NCP2 + part * 4);
        acc.x += v.x * c; acc.y += v.y * c; acc.z += v.z * c; acc.w += v.w * c;
    }

    float sl = din * din;
    float4 h = *reinterpret_cast<const float4*>(g_h2 + node * NCP2 + part * 4);
    float* pool = g_pool + g * NC;

    float res[4] = { acc.x + h.x * sl, acc.y + h.y * sl,
                     acc.z + h.z * sl, acc.w + h.w * sl };
#pragma unroll
    for (int c = 0; c < 4; c++) {
        int col = part * 4 + c;
        if (col < NC) atomicAdd(pool + col, res[c] + b2[col]);
    }
    if (part == 0) {
        atomicAdd(&g_gcnt[g], 1.0f);
        g_cnt_i[node] = 0;                    // self-clean for next call
    }
}

// ---------------- finalize: mean + log_softmax (+ self-clean pool) ----------------------
__global__ void k_softmax(float* __restrict__ out) {
    int g = threadIdx.x;
    if (g >= NG) return;
    float cnt = fmaxf(g_gcnt[g], 1.0f);
    float p[NC];
    float m = -1e30f;
#pragma unroll
    for (int o = 0; o < NC; o++) { p[o] = g_pool[g * NC + o] / cnt; m = fmaxf(m, p[o]); }
    float s = 0.f;
#pragma unroll
    for (int o = 0; o < NC; o++) s += __expf(p[o] - m);
    float l = logf(s);
#pragma unroll
    for (int o = 0; o < NC; o++) {
        out[g * NC + o] = p[o] - m - l;
        g_pool[g * NC + o] = 0.f;             // self-clean for next call
    }
    g_gcnt[g] = 0.f;
}

// ---------------- launcher ----------------------------------------------------------------
extern "C" void kernel_launch(void* const* d_in, const int* in_sizes, int n_in,
                              void* d_out, int out_size) {
    const float* x     = (const float*)d_in[0];
    const int*   ei    = (const int*)d_in[1];    // int32 (jax default int)
    const int*   batch = (const int*)d_in[2];
    const float* W1    = (const float*)d_in[3];
    const float* b1    = (const float*)d_in[4];
    const float* W2    = (const float*)d_in[5];
    const float* b2    = (const float*)d_in[6];
    float* out = (float*)d_out;

    const int TB = 256;
    const int nodeBlocks  = (N_NODES + TB - 1) / TB;          // 391
    const int node4Blocks = (4 * N_NODES + TB - 1) / TB;      // 1563
    const int fillBlocks  = (N_EDGES / 8 + TB - 1) / TB;      // 1563

    k_pre1<<<PRE1_BLOCKS, TB>>>(x, W1, ei);           // launch 1
    k_scan_block<<<N_SCAN_BLOCKS, SCAN_BLK>>>();      // launch 2
    k_scan_finish<<<nodeBlocks, TB>>>();              // launch 3
    k_fill<<<fillBlocks, TB>>>(ei);                   // launch 4  <- ncu slot
    k_gather1<<<node4Blocks, TB>>>(b1, W2);           // launch 5
    k_gather2<<<node4Blocks, TB>>>(b2, batch);        // launch 6
    k_softmax<<<1, 64>>>(out);                        // launch 7
}